// round 5
// baseline (speedup 1.0000x reference)
#include <cuda_runtime.h>

// ---------------------------------------------------------------------------
// Problem constants (tables are __device__ constexpr: usable in device code,
// still constant-foldable from host code)
// ---------------------------------------------------------------------------
namespace {
constexpr int NPOST = 100000, NUSER = 50000, NENT = 20000;
constexpr int NTOT = NPOST + NUSER + NENT;          // 170000

__device__ constexpr int ECNT[6] = {100000, 200000, 200000, 400000, 400000, 250000};
__device__ constexpr int SRCT[6] = {1, 1, 0, 1, 1, 0};
__device__ constexpr int DSTT[6] = {0, 0, 2, 1, 1, 0};
__device__ constexpr int NTY[3]  = {NPOST, NUSER, NENT};
__device__ constexpr long long ACCO[3] = {0, 6400000, 9600000};  // node-type base (floats)

// scratch layout (floats)
constexpr long long OFF_HA  = 0;                        // NTOT*64 = 10,880,000
constexpr long long OFF_HB  = 10880000;
constexpr long long OFF_HS  = 21760000;                 // 51,200,000
constexpr long long OFF_ALS = 72960000;                 // 800,000
constexpr long long OFF_ALD = 73760000;                 // 840,000
constexpr long long OFF_M   = 74600000;                 // 840,000 (ints)
constexpr long long OFF_S   = 75440000;                 // 840,000
constexpr long long OFF_P   = 76280000;                 // 3,100,000
constexpr long long TOTAL_SCRATCH = 79380000;

// per-relation sub-offsets (floats)
__device__ constexpr long long HSO[6]  = {0, 6400000, 12800000, 25600000, 32000000, 38400000};
__device__ constexpr long long ALSO[6] = {0, 100000, 200000, 400000, 500000, 600000};
__device__ constexpr long long ALDO[6] = {0, 200000, 400000, 440000, 540000, 640000};
__device__ constexpr long long PO[6]   = {0, 200000, 600000, 1000000, 1800000, 2600000};

// block-prefix tables: 1 thread/edge @256  and 16 threads/edge @256
__device__ constexpr int EBO[6] = {0, 391, 1173, 1955, 3518, 5081};      // total 6058
__device__ constexpr int ABO[6] = {0, 6250, 18750, 31250, 56250, 81250}; // total 96875
}  // namespace

__device__ __align__(256) float g_scratch[TOTAL_SCRATCH];

// ---------------------------------------------------------------------------
// f32x2 packed-FMA helpers (FFMA2 — PTX-only, ptxas never auto-fuses)
// ---------------------------------------------------------------------------
__device__ __forceinline__ unsigned long long pk2(float x, float y) {
    unsigned long long r;
    asm("mov.b64 %0, {%1, %2};" : "=l"(r) : "f"(x), "f"(y));
    return r;
}
__device__ __forceinline__ void fma2(unsigned long long& a, unsigned long long x,
                                     unsigned long long y) {
    asm("fma.rn.f32x2 %0, %1, %2, %0;" : "+l"(a) : "l"(x), "l"(y));
}
__device__ __forceinline__ float lo32(unsigned long long v) {
    return __int_as_float((int)(unsigned)v);
}
__device__ __forceinline__ float hi32(unsigned long long v) {
    return __int_as_float((int)(unsigned)(v >> 32));
}

// ---------------------------------------------------------------------------
// Ordered-int float max helpers
// ---------------------------------------------------------------------------
__device__ __forceinline__ int f2o(float f) {
    int i = __float_as_int(f);
    return i >= 0 ? i : (i ^ 0x7FFFFFFF);
}
__device__ __forceinline__ float o2f(int k) {
    return __int_as_float(k >= 0 ? k : (k ^ 0x7FFFFFFF));
}
#define NEG_INF_KEY ((int)0x807FFFFF)

// ---------------------------------------------------------------------------
// GEMM tile core:  C[M, BN] = A[M, K] @ B[BN, K]^T  (+bias, +relu)
// BM=128, BK=16, TM=8 (paired as 4 f32x2 lanes), TN=4. 16 FFMA2/kk.
// ---------------------------------------------------------------------------
template <int BN, bool BIAS, bool RELU>
__device__ __forceinline__ void gemm_tile(const float* __restrict__ A,
                                          const float* __restrict__ B,
                                          const float* __restrict__ bias,
                                          float* __restrict__ C, int M, int K, int m0) {
    constexpr int BM = 128, BK = 16, TM = 8, TN = 4;
    constexpr int THREADS = (BM / TM) * (BN / TN);
    __shared__ __align__(16) float As[BK][BM + 4];
    __shared__ __align__(16) float Bs[BK][BN + 4];

    const int t  = threadIdx.x;
    const int jc = (t % (BN / TN)) * TN;
    const int ir = (t / (BN / TN)) * TM;

    unsigned long long accp[TM / 2][TN];
#pragma unroll
    for (int q = 0; q < TM / 2; q++)
#pragma unroll
        for (int j = 0; j < TN; j++) accp[q][j] = 0ULL;

    for (int k0 = 0; k0 < K; k0 += BK) {
        constexpr int A4 = BM * BK / 4;
#pragma unroll
        for (int q = t; q < A4; q += THREADS) {
            int row = q / (BK / 4);
            int kq  = (q % (BK / 4)) * 4;
            int gr  = m0 + row;
            if (gr >= M) gr = M - 1;  // clamp; stores guarded
            float4 v = *reinterpret_cast<const float4*>(&A[(size_t)gr * K + k0 + kq]);
            As[kq][row] = v.x; As[kq + 1][row] = v.y;
            As[kq + 2][row] = v.z; As[kq + 3][row] = v.w;
        }
        constexpr int B4 = BN * BK / 4;
#pragma unroll
        for (int q = t; q < B4; q += THREADS) {
            int row = q / (BK / 4);
            int kq  = (q % (BK / 4)) * 4;
            float4 v = *reinterpret_cast<const float4*>(&B[(size_t)row * K + k0 + kq]);
            Bs[kq][row] = v.x; Bs[kq + 1][row] = v.y;
            Bs[kq + 2][row] = v.z; Bs[kq + 3][row] = v.w;
        }
        __syncthreads();
#pragma unroll
        for (int kk = 0; kk < BK; kk++) {
            ulonglong2 A0 = *reinterpret_cast<const ulonglong2*>(&As[kk][ir]);
            ulonglong2 A1 = *reinterpret_cast<const ulonglong2*>(&As[kk][ir + 4]);
            float4 b4 = *reinterpret_cast<const float4*>(&Bs[kk][jc]);
            unsigned long long bb0 = pk2(b4.x, b4.x), bb1 = pk2(b4.y, b4.y);
            unsigned long long bb2 = pk2(b4.z, b4.z), bb3 = pk2(b4.w, b4.w);
            fma2(accp[0][0], A0.x, bb0); fma2(accp[0][1], A0.x, bb1);
            fma2(accp[0][2], A0.x, bb2); fma2(accp[0][3], A0.x, bb3);
            fma2(accp[1][0], A0.y, bb0); fma2(accp[1][1], A0.y, bb1);
            fma2(accp[1][2], A0.y, bb2); fma2(accp[1][3], A0.y, bb3);
            fma2(accp[2][0], A1.x, bb0); fma2(accp[2][1], A1.x, bb1);
            fma2(accp[2][2], A1.x, bb2); fma2(accp[2][3], A1.x, bb3);
            fma2(accp[3][0], A1.y, bb0); fma2(accp[3][1], A1.y, bb1);
            fma2(accp[3][2], A1.y, bb2); fma2(accp[3][3], A1.y, bb3);
        }
        __syncthreads();
    }

#pragma unroll
    for (int q = 0; q < TM / 2; q++) {
        int r0 = m0 + ir + 2 * q;
        int r1 = r0 + 1;
#pragma unroll
        for (int j = 0; j < TN; j++) {
            float v0 = lo32(accp[q][j]), v1 = hi32(accp[q][j]);
            if (BIAS) { float b = bias[jc + j]; v0 += b; v1 += b; }
            if (RELU) { v0 = fmaxf(v0, 0.f); v1 = fmaxf(v1, 0.f); }
            if (r0 < M) C[(size_t)r0 * BN + jc + j] = v0;
            if (r1 < M) C[(size_t)r1 * BN + jc + j] = v1;
        }
    }
}

template <int BN, bool BIAS, bool RELU>
__global__ void gemm_k(const float* __restrict__ A, const float* __restrict__ B,
                       const float* __restrict__ bias, float* __restrict__ C, int M, int K) {
    gemm_tile<BN, BIAS, RELU>(A, B, bias, C, M, K, blockIdx.x * 128);
}

// Batched hs GEMM: blockIdx.y = relation; BN=128, K=64.
struct HsJobs { const float* A[6]; const float* B[6]; float* C[6]; int M[6]; };
__global__ void hs_gemm_b(HsJobs J) {
    int r = blockIdx.y;
    int m0 = blockIdx.x * 128;
    if (m0 >= J.M[r]) return;
    gemm_tile<128, false, false>(J.A[r], J.B[r], nullptr, J.C[r], J.M[r], 64, m0);
}

// ---------------------------------------------------------------------------
// Batched attention logits: 12 jobs (6 src-side + 6 dst-side), blockIdx.y = job
// al[n,h] = x[n,:] @ v[h,:],  v[h,k] = sum_c W[h*64+c,k]*a[h,c]
// ---------------------------------------------------------------------------
struct LogitJobs { const float* x[12]; const float* W[12]; const float* a[12];
                   float* out[12]; int N[12]; };
__global__ void logits_b(LogitJobs J) {
    int z = blockIdx.y;
    __shared__ float v[2][64];
    const int t = threadIdx.x;
    if (t < 128) {
        int h = t >> 6, k = t & 63;
        const float* W = J.W[z];
        const float* a = J.a[z];
        float sum = 0.f;
#pragma unroll
        for (int c = 0; c < 64; c++) sum += W[(h * 64 + c) * 64 + k] * a[h * 64 + c];
        v[h][k] = sum;
    }
    __syncthreads();
    int g = blockIdx.x * 256 + t;
    if (g < J.N[z] * 2) {
        int n = g >> 1, h = g & 1;
        const float4* xr = reinterpret_cast<const float4*>(J.x[z] + (size_t)n * 64);
        float s = 0.f;
#pragma unroll
        for (int k4 = 0; k4 < 16; k4++) {
            float4 xv = xr[k4];
            s += xv.x * v[h][k4 * 4] + xv.y * v[h][k4 * 4 + 1] +
                 xv.z * v[h][k4 * 4 + 2] + xv.w * v[h][k4 * 4 + 3];
        }
        J.out[z][g] = s;
    }
}

// ---------------------------------------------------------------------------
// Fused init: zero acc (NTOT*64), zero s (840k), set m keys (840k)
// ---------------------------------------------------------------------------
__global__ void init_all(float* __restrict__ acc, int* __restrict__ m, float* __restrict__ s) {
    const long long A4 = (long long)NTOT * 64 / 4;   // 2,720,000
    const long long MS4 = 840000 / 4;                // 210,000
    long long i = (long long)blockIdx.x * 256 + threadIdx.x;
    if (i < A4) {
        reinterpret_cast<float4*>(acc)[i] = make_float4(0.f, 0.f, 0.f, 0.f);
    } else if (i < A4 + MS4) {
        long long j = i - A4;
        reinterpret_cast<int4*>(m)[j] = make_int4(NEG_INF_KEY, NEG_INF_KEY, NEG_INF_KEY, NEG_INF_KEY);
        reinterpret_cast<float4*>(s)[j] = make_float4(0.f, 0.f, 0.f, 0.f);
    }
}

// ---------------------------------------------------------------------------
// Batched edge passes (block-prefix -> relation)
// ---------------------------------------------------------------------------
struct EPtrs { const int* src[6]; const int* dst[6]; };

__device__ __forceinline__ int find_rel(int bx, const int* bo) {
    int r = 5;
    if (bx < bo[1]) r = 0;
    else if (bx < bo[2]) r = 1;
    else if (bx < bo[3]) r = 2;
    else if (bx < bo[4]) r = 3;
    else if (bx < bo[5]) r = 4;
    return r;
}

__global__ void edge_max_b(EPtrs P, float* __restrict__ S) {
    int bx = blockIdx.x;
    const int bo[6] = {EBO[0], EBO[1], EBO[2], EBO[3], EBO[4], EBO[5]};
    int r = find_rel(bx, bo);
    int e = (bx - bo[r]) * 256 + threadIdx.x;
    if (e >= ECNT[r]) return;
    int sn = P.src[r][e], d = P.dst[r][e];
    float2 as2 = *reinterpret_cast<const float2*>(S + OFF_ALS + ALSO[r] + (size_t)sn * 2);
    float2 ad2 = *reinterpret_cast<const float2*>(S + OFF_ALD + ALDO[r] + (size_t)d * 2);
    float v0 = as2.x + ad2.x; v0 = v0 < 0.f ? 0.2f * v0 : v0;
    float v1 = as2.y + ad2.y; v1 = v1 < 0.f ? 0.2f * v1 : v1;
    int* m = reinterpret_cast<int*>(S + OFF_M) + ALDO[r] + (size_t)d * 2;
    atomicMax(m, f2o(v0));
    atomicMax(m + 1, f2o(v1));
}

__global__ void edge_p_b(EPtrs P, float* __restrict__ S) {
    int bx = blockIdx.x;
    const int bo[6] = {EBO[0], EBO[1], EBO[2], EBO[3], EBO[4], EBO[5]};
    int r = find_rel(bx, bo);
    int e = (bx - bo[r]) * 256 + threadIdx.x;
    if (e >= ECNT[r]) return;
    int sn = P.src[r][e], d = P.dst[r][e];
    float2 as2 = *reinterpret_cast<const float2*>(S + OFF_ALS + ALSO[r] + (size_t)sn * 2);
    float2 ad2 = *reinterpret_cast<const float2*>(S + OFF_ALD + ALDO[r] + (size_t)d * 2);
    float v0 = as2.x + ad2.x; v0 = v0 < 0.f ? 0.2f * v0 : v0;
    float v1 = as2.y + ad2.y; v1 = v1 < 0.f ? 0.2f * v1 : v1;
    const int* m = reinterpret_cast<const int*>(S + OFF_M) + ALDO[r] + (size_t)d * 2;
    float p0 = __expf(v0 - o2f(m[0]));
    float p1 = __expf(v1 - o2f(m[1]));
    *reinterpret_cast<float2*>(S + OFF_P + PO[r] + (size_t)e * 2) = make_float2(p0, p1);
    float* ss = S + OFF_S + ALDO[r] + (size_t)d * 2;
    atomicAdd(ss, p0);
    atomicAdd(ss + 1, p1);
}

__global__ void rcp_all(float* __restrict__ s) {
    int i = blockIdx.x * 256 + threadIdx.x;
    if (i < 210000) {
        float4 v = reinterpret_cast<float4*>(s)[i];
        v.x = 1.0f / (v.x + 1e-16f);
        v.y = 1.0f / (v.y + 1e-16f);
        v.z = 1.0f / (v.z + 1e-16f);
        v.w = 1.0f / (v.w + 1e-16f);
        reinterpret_cast<float4*>(s)[i] = v;
    }
}

__global__ void edge_acc_b(EPtrs P, float* __restrict__ S, float* __restrict__ nxt) {
    int bx = blockIdx.x;
    const int bo[6] = {ABO[0], ABO[1], ABO[2], ABO[3], ABO[4], ABO[5]};
    int r = find_rel(bx, bo);
    int t = threadIdx.x;
    int e = (bx - bo[r]) * 16 + (t >> 4);
    if (e >= ECNT[r]) return;
    int lane = t & 15;
    int sn = P.src[r][e], d = P.dst[r][e];
    float2 pp = *reinterpret_cast<const float2*>(S + OFF_P + PO[r] + (size_t)e * 2);
    const float* rs = S + OFF_S + ALDO[r] + (size_t)d * 2;
    float a0 = 0.5f * pp.x * rs[0];
    float a1 = 0.5f * pp.y * rs[1];
    const float* hrow = S + OFF_HS + HSO[r] + (size_t)sn * 128;
    float4 h0 = *reinterpret_cast<const float4*>(hrow + lane * 4);
    float4 h1 = *reinterpret_cast<const float4*>(hrow + 64 + lane * 4);
    float4 rv;
    rv.x = a0 * h0.x + a1 * h1.x;
    rv.y = a0 * h0.y + a1 * h1.y;
    rv.z = a0 * h0.z + a1 * h1.z;
    rv.w = a0 * h0.w + a1 * h1.w;
    float* dp = nxt + ACCO[DSTT[r]] + (size_t)d * 64 + lane * 4;
    asm volatile("red.global.add.v4.f32 [%0], {%1,%2,%3,%4};"
                 :: "l"(dp), "f"(rv.x), "f"(rv.y), "f"(rv.z), "f"(rv.w) : "memory");
}

// ---------------------------------------------------------------------------
// Fused finalize over all node types: h = relu(acc + sum relation biases)
// ---------------------------------------------------------------------------
__global__ void finalize_all(float* __restrict__ h, const float* __restrict__ gatb, int l) {
    long long i4 = (long long)blockIdx.x * 256 + threadIdx.x;
    const long long N4 = (long long)NTOT * 16;  // 2,720,000 float4s
    if (i4 >= N4) return;
    long long node = i4 >> 4;
    int c = (int)(i4 & 15) * 4;
    const float* gb = gatb + (long long)l * 6 * 64;
    float4 b;
    if (node < NPOST) {
        float4 b0 = *reinterpret_cast<const float4*>(gb + 0 * 64 + c);
        float4 b1 = *reinterpret_cast<const float4*>(gb + 1 * 64 + c);
        float4 b5 = *reinterpret_cast<const float4*>(gb + 5 * 64 + c);
        b = make_float4(b0.x + b1.x + b5.x, b0.y + b1.y + b5.y,
                        b0.z + b1.z + b5.z, b0.w + b1.w + b5.w);
    } else if (node < NPOST + NUSER) {
        float4 b3 = *reinterpret_cast<const float4*>(gb + 3 * 64 + c);
        float4 b4 = *reinterpret_cast<const float4*>(gb + 4 * 64 + c);
        b = make_float4(b3.x + b4.x, b3.y + b4.y, b3.z + b4.z, b3.w + b4.w);
    } else {
        b = *reinterpret_cast<const float4*>(gb + 2 * 64 + c);
    }
    float4 v = reinterpret_cast<float4*>(h)[i4];
    v.x = fmaxf(v.x + b.x, 0.f);
    v.y = fmaxf(v.y + b.y, 0.f);
    v.z = fmaxf(v.z + b.z, 0.f);
    v.w = fmaxf(v.w + b.w, 0.f);
    reinterpret_cast<float4*>(h)[i4] = v;
}

// ---------------------------------------------------------------------------
// Classifier: out[n] = relu(h[n] @ w1^T + b1) @ w2^T + b2  (one warp / node)
// ---------------------------------------------------------------------------
__global__ void cls_kernel(const float* __restrict__ h, const float* __restrict__ w1,
                           const float* __restrict__ b1, const float* __restrict__ w2,
                           const float* __restrict__ b2, float* __restrict__ out, int N) {
    __shared__ float sw1t[64 * 33];
    __shared__ float sw2[32], sb1[32];
    for (int i = threadIdx.x; i < 2048; i += blockDim.x) {
        int j = i / 64, k = i % 64;
        sw1t[k * 33 + j] = w1[i];
    }
    if (threadIdx.x < 32) { sw2[threadIdx.x] = w2[threadIdx.x]; sb1[threadIdx.x] = b1[threadIdx.x]; }
    __syncthreads();
    int warp = threadIdx.x >> 5, lane = threadIdx.x & 31;
    int n = blockIdx.x * 8 + warp;
    if (n >= N) return;
    const float4* hr = reinterpret_cast<const float4*>(h + (size_t)n * 64);
    float t = 0.f;
#pragma unroll
    for (int k4 = 0; k4 < 16; k4++) {
        float4 hv = hr[k4];
        int k = k4 * 4;
        t += hv.x * sw1t[(k    ) * 33 + lane] + hv.y * sw1t[(k + 1) * 33 + lane] +
             hv.z * sw1t[(k + 2) * 33 + lane] + hv.w * sw1t[(k + 3) * 33 + lane];
    }
    t = fmaxf(t + sb1[lane], 0.f);
    float o = t * sw2[lane];
#pragma unroll
    for (int off = 16; off; off >>= 1) o += __shfl_down_sync(0xffffffffu, o, off);
    if (lane == 0) out[n] = o + b2[0];
}

// ---------------------------------------------------------------------------
// Host orchestration (graph-capturable)
// ---------------------------------------------------------------------------
extern "C" void kernel_launch(void* const* d_in, const int* in_sizes, int n_in,
                              void* d_out, int out_size) {
    float* S = nullptr;
    cudaGetSymbolAddress((void**)&S, g_scratch);

    const float* x_post = (const float*)d_in[0];
    const float* x_user = (const float*)d_in[1];
    const float* x_ent  = (const float*)d_in[2];
    EPtrs EP;
    for (int r = 0; r < 6; r++) {
        EP.src[r] = (const int*)d_in[3 + 2 * r];
        EP.dst[r] = (const int*)d_in[4 + 2 * r];
    }
    const float* pw = (const float*)d_in[15]; const float* pb = (const float*)d_in[16];
    const float* uw = (const float*)d_in[17]; const float* ub = (const float*)d_in[18];
    const float* ew = (const float*)d_in[19]; const float* eb = (const float*)d_in[20];
    const float* Wsrc = (const float*)d_in[21];
    const float* Wdst = (const float*)d_in[22];
    const float* asrc = (const float*)d_in[23];
    const float* adst = (const float*)d_in[24];
    const float* gatb = (const float*)d_in[25];
    const float* w1 = (const float*)d_in[26]; const float* b1 = (const float*)d_in[27];
    const float* w2 = (const float*)d_in[28]; const float* b2 = (const float*)d_in[29];
    float* out = (float*)d_out;

    float* hA = S + OFF_HA;
    float* hB = S + OFF_HB;

    const int srcT[6] = {1, 1, 0, 1, 1, 0};
    const int dstT[6] = {0, 0, 2, 1, 1, 0};
    const int nty[3] = {NPOST, NUSER, NENT};
    const long long acco[3] = {0, 6400000, 9600000};
    const long long hso[6]  = {0, 6400000, 12800000, 25600000, 32000000, 38400000};
    const long long also_[6] = {0, 100000, 200000, 400000, 500000, 600000};
    const long long aldo[6] = {0, 200000, 400000, 440000, 540000, 640000};

    // Input projections
    gemm_k<64, true, false><<<(NPOST + 127) / 128, 256>>>(x_post, pw, pb, hA + acco[0], NPOST, 768);
    gemm_k<64, true, false><<<(NUSER + 127) / 128, 256>>>(x_user, uw, ub, hA + acco[1], NUSER, 32);
    gemm_k<64, true, false><<<(NENT  + 127) / 128, 256>>>(x_ent,  ew, eb, hA + acco[2], NENT, 64);

    for (int l = 0; l < 2; l++) {
        float* cur = l ? hB : hA;
        float* nxt = l ? hA : hB;

        init_all<<<11446, 256>>>(nxt, (int*)(S + OFF_M), S + OFF_S);

        HsJobs HJ;
        LogitJobs LJ;
        for (int r = 0; r < 6; r++) {
            HJ.A[r] = cur + acco[srcT[r]];
            HJ.B[r] = Wsrc + (long long)(l * 6 + r) * 8192;
            HJ.C[r] = S + OFF_HS + hso[r];
            HJ.M[r] = nty[srcT[r]];
            LJ.x[r] = cur + acco[srcT[r]];
            LJ.W[r] = Wsrc + (long long)(l * 6 + r) * 8192;
            LJ.a[r] = asrc + (long long)(l * 6 + r) * 128;
            LJ.out[r] = S + OFF_ALS + also_[r];
            LJ.N[r] = nty[srcT[r]];
            LJ.x[6 + r] = cur + acco[dstT[r]];
            LJ.W[6 + r] = Wdst + (long long)(l * 6 + r) * 8192;
            LJ.a[6 + r] = adst + (long long)(l * 6 + r) * 128;
            LJ.out[6 + r] = S + OFF_ALD + aldo[r];
            LJ.N[6 + r] = nty[dstT[r]];
        }
        hs_gemm_b<<<dim3(782, 6), 512>>>(HJ);
        logits_b<<<dim3(782, 12), 256>>>(LJ);
        edge_max_b<<<6058, 256>>>(EP, S);
        edge_p_b<<<6058, 256>>>(EP, S);
        rcp_all<<<(210000 + 255) / 256, 256>>>(S + OFF_S);
        edge_acc_b<<<96875, 256>>>(EP, S, nxt);
        finalize_all<<<(2720000 + 255) / 256, 256>>>(nxt, gatb, l);
    }

    cls_kernel<<<(NPOST + 7) / 8, 256>>>(hA + acco[0], w1, b1, w2, b2, out, NPOST);
}